// round 2
// baseline (speedup 1.0000x reference)
#include <cuda_runtime.h>
#include <math.h>

#define B_ 64
#define C_ 81
#define N_ 8732
#define TILE_N 1024
#define TILES 9          // ceil(8732/1024)
#define THREADS 256

// scratch (no allocations allowed)
__device__ float g_closs[(size_t)B_ * N_];
__device__ float g_part[B_ * TILES * 4];
__device__ int   g_is64;

__device__ __forceinline__ float smooth_l1(float x) {
    float ax = fabsf(x);
    return ax < 1.0f ? 0.5f * ax * ax : ax - 0.5f;
}

// Detect glabel dtype: int64 labels (0..80, non-negative) have all-zero high
// words, so every odd int32 lane is 0. For true int32 random labels the odds
// of 256 consecutive odd lanes being 0 is (1/81)^256 ~ 0.
__global__ void mbl_detect(const int* __restrict__ gl) {
    int nz = 0;
    for (int i = 1; i < 512; i += 2) nz += (gl[i] != 0);
    g_is64 = (nz == 0) ? 1 : 0;
}

__device__ __forceinline__ void load_labels(const void* glabel, int b, int n0,
                                            int is64, int lab[4]) {
    if (is64) {
        const long long* gl = (const long long*)glabel + (size_t)b * N_ + n0;
        #pragma unroll
        for (int j = 0; j < 4; j++) lab[j] = (int)gl[j];
    } else {
        const int* gl = (const int*)glabel + (size_t)b * N_ + n0;
        #pragma unroll
        for (int j = 0; j < 4; j++) lab[j] = gl[j];
    }
}

__global__ __launch_bounds__(THREADS) void mbl_k1(
    const float* __restrict__ ploc, const float* __restrict__ plabel,
    const float* __restrict__ gloc, const void* __restrict__ glabel,
    const float* __restrict__ dbox)
{
    const int tile = blockIdx.x;
    const int b    = blockIdx.y;
    const int t    = threadIdx.x;
    const int n0   = tile * TILE_N + t * 4;
    const bool act = (n0 < N_);   // N_ % 4 == 0, so full float4 or nothing

    float np = 0.f, ll = 0.f, cm = 0.f, ca = 0.f;

    if (act) {
        int lab[4];
        load_labels(glabel, b, n0, g_is64, lab);

        // ---- online log-softmax over C=81 (1 exp / element) ----
        const float* pl = plabel + (size_t)b * C_ * N_ + n0;
        float m[4], s[4], xl[4];
        {
            float4 v = *(const float4*)pl;
            float xs[4] = {v.x, v.y, v.z, v.w};
            #pragma unroll
            for (int j = 0; j < 4; j++) {
                m[j] = xs[j];
                s[j] = 1.f;
                xl[j] = (lab[j] == 0) ? xs[j] : 0.f;
            }
        }
        #pragma unroll 4
        for (int c = 1; c < C_; c++) {
            float4 v = *(const float4*)(pl + (size_t)c * N_);
            float xs[4] = {v.x, v.y, v.z, v.w};
            #pragma unroll
            for (int j = 0; j < 4; j++) {
                float x = xs[j];
                float d = x - m[j];
                float e = __expf(d > 0.f ? -d : d);   // exp(-|d|), one MUFU
                if (d > 0.f) { s[j] = fmaf(s[j], e, 1.f); m[j] = x; }
                else         { s[j] += e; }
                if (c == lab[j]) xl[j] = x;
            }
        }
        float closs[4];
        #pragma unroll
        for (int j = 0; j < 4; j++) closs[j] = m[j] + __logf(s[j]) - xl[j];

        // ---- localization smooth-L1 ----
        float pp[4][4], gg[4][4], dd[4][4];
        #pragma unroll
        for (int k = 0; k < 4; k++) {
            float4 pv = *(const float4*)(ploc + ((size_t)b * 4 + k) * N_ + n0);
            float4 gv = *(const float4*)(gloc + ((size_t)b * 4 + k) * N_ + n0);
            float4 dv = *(const float4*)(dbox + (size_t)k * N_ + n0);
            pp[k][0]=pv.x; pp[k][1]=pv.y; pp[k][2]=pv.z; pp[k][3]=pv.w;
            gg[k][0]=gv.x; gg[k][1]=gv.y; gg[k][2]=gv.z; gg[k][3]=gv.w;
            dd[k][0]=dv.x; dd[k][1]=dv.y; dd[k][2]=dv.z; dd[k][3]=dv.w;
        }
        #pragma unroll
        for (int j = 0; j < 4; j++) {
            float gx = __fdividef(gg[0][j] - dd[0][j], dd[2][j]);
            float gy = __fdividef(gg[1][j] - dd[1][j], dd[3][j]);
            float gw = __logf(__fdividef(gg[2][j], dd[2][j]));
            float gh = __logf(__fdividef(gg[3][j], dd[3][j]));
            float loc = smooth_l1(pp[0][j] - gx) + smooth_l1(pp[1][j] - gy)
                      + smooth_l1(pp[2][j] - gw) + smooth_l1(pp[3][j] - gh);
            bool mk = lab[j] > 0;
            np += mk ? 1.f : 0.f;
            ll += mk ? loc : 0.f;
            cm += mk ? closs[j] : 0.f;
            ca += closs[j];
        }
        *(float4*)(g_closs + (size_t)b * N_ + n0) =
            make_float4(closs[0], closs[1], closs[2], closs[3]);
    }

    // ---- deterministic block reduction of (np, ll, cm, ca) ----
    __shared__ float4 red[THREADS];
    red[t] = make_float4(np, ll, cm, ca);
    __syncthreads();
    for (int st = THREADS / 2; st > 0; st >>= 1) {
        if (t < st) {
            float4 a = red[t], c4 = red[t + st];
            red[t] = make_float4(a.x + c4.x, a.y + c4.y, a.z + c4.z, a.w + c4.w);
        }
        __syncthreads();
    }
    if (t == 0) {
        float* o = &g_part[(b * TILES + tile) * 4];
        float4 r = red[0];
        o[0] = r.x; o[1] = r.y; o[2] = r.z; o[3] = r.w;
    }
}

// Single-block finalize: reduce partials, per-batch scale, mean.
// Exact hard-negative-mining fallback (counting rank) if 3*num_pos < N;
// with this data distribution neg_mask is all-true so the fast path runs.
__global__ __launch_bounds__(256) void mbl_k2(
    const void* __restrict__ glabel, float* __restrict__ out)
{
    __shared__ float s_np[B_], s_loc[B_], s_cm[B_], s_sel[B_];
    __shared__ int   s_fb[B_];
    __shared__ float s_con[N_];          // 34.9 KB
    __shared__ float red[256];
    const int t = threadIdx.x;
    const int is64 = g_is64;

    if (t < B_) {
        float np = 0.f, ll = 0.f, cm = 0.f, ca = 0.f;
        for (int i = 0; i < TILES; i++) {
            const float* p = &g_part[(t * TILES + i) * 4];
            np += p[0]; ll += p[1]; cm += p[2]; ca += p[3];
        }
        s_np[t] = np; s_loc[t] = ll; s_cm[t] = cm;
        s_sel[t] = ca;                       // default: neg_mask all-true
        int npi = (int)np;
        s_fb[t] = (npi > 0 && 3 * npi < N_) ? 1 : 0;
    }
    __syncthreads();

    for (int b = 0; b < B_; b++) {
        if (!s_fb[b]) continue;              // uniform (shared) condition
        // build con_neg in shared
        for (int n = t; n < N_; n += 256) {
            float cl = g_closs[(size_t)b * N_ + n];
            long long lv = is64 ? ((const long long*)glabel)[(size_t)b * N_ + n]
                                : (long long)((const int*)glabel)[(size_t)b * N_ + n];
            s_con[n] = (lv > 0) ? 0.f : cl;
        }
        __syncthreads();
        int K = min(3 * (int)s_np[b], N_);
        float sel = 0.f;
        for (int n = t; n < N_; n += 256) {
            float v = s_con[n];
            int rank = 0;
            for (int q = 0; q < N_; q++) {
                float u = s_con[q];
                rank += (u > v) || (u == v && q < n);
            }
            if (rank < K) sel += g_closs[(size_t)b * N_ + n];
        }
        red[t] = sel; __syncthreads();
        for (int st = 128; st > 0; st >>= 1) {
            if (t < st) red[t] += red[t + st];
            __syncthreads();
        }
        if (t == 0) s_sel[b] = red[0];
        __syncthreads();
    }

    __shared__ float vals[B_];
    if (t < B_) {
        float np = s_np[t];
        float total = s_loc[t] + s_cm[t] + s_sel[t];
        float nm = np > 0.f ? 1.f : 0.f;
        float npos = fmaxf(np, 1e-6f);
        vals[t] = total * nm / npos;
    }
    __syncthreads();
    if (t == 0) {
        float sum = 0.f;
        for (int i = 0; i < B_; i++) sum += vals[i];
        out[0] = sum / (float)B_;
    }
}

extern "C" void kernel_launch(void* const* d_in, const int* in_sizes, int n_in,
                              void* d_out, int out_size)
{
    const float* ploc   = (const float*)d_in[0];
    const float* plabel = (const float*)d_in[1];
    const float* gloc   = (const float*)d_in[2];
    const void*  glabel = d_in[3];
    const float* dbox   = (const float*)d_in[4];

    mbl_detect<<<1, 1>>>((const int*)glabel);
    mbl_k1<<<dim3(TILES, B_), THREADS>>>(ploc, plabel, gloc, glabel, dbox);
    mbl_k2<<<1, 256>>>(glabel, (float*)d_out);
}

// round 4
// speedup vs baseline: 1.1500x; 1.1500x over previous
#include <cuda_runtime.h>
#include <math.h>

#define B_ 64
#define C_ 81
#define N_ 8732
#define TILE_N 1024
#define TILES 9          // ceil(8732/1024)
#define THREADS 256

// scratch (no allocations allowed)
__device__ float g_closs[(size_t)B_ * N_];
__device__ float g_part[B_ * TILES * 4];

__device__ __forceinline__ float smooth_l1(float x) {
    float ax = fabsf(x);
    return ax < 1.0f ? 0.5f * ax * ax : ax - 0.5f;
}

// In-block dtype probe: int64 labels (values 0..80, non-negative) have all-zero
// high words -> every odd int32 lane of the buffer is 0. For genuine int32
// random labels, P(256 odd lanes all zero) = (1/81)^256 ~ 0.
// All 256 threads read one lane each (coalesced 2KB, L2-hit after 1st block).
__device__ __forceinline__ int probe_is64(const void* glabel, int t) {
    int w = ((const int*)glabel)[2 * t + 1];
    int any_nz = __syncthreads_or(w != 0);
    return any_nz ? 0 : 1;
}

__device__ __forceinline__ void load_labels(const void* glabel, int b, int n0,
                                            int is64, int lab[4]) {
    if (is64) {
        const long long* gl = (const long long*)glabel + (size_t)b * N_ + n0;
        #pragma unroll
        for (int j = 0; j < 4; j++) lab[j] = (int)gl[j];
    } else {
        const int* gl = (const int*)glabel + (size_t)b * N_ + n0;
        #pragma unroll
        for (int j = 0; j < 4; j++) lab[j] = gl[j];
    }
}

__global__ __launch_bounds__(THREADS) void mbl_k1(
    const float* __restrict__ ploc, const float* __restrict__ plabel,
    const float* __restrict__ gloc, const void* __restrict__ glabel,
    const float* __restrict__ dbox)
{
    const int tile = blockIdx.x;
    const int b    = blockIdx.y;
    const int t    = threadIdx.x;
    const int n0   = tile * TILE_N + t * 4;
    const bool act = (n0 < N_);   // N_ % 4 == 0, so full float4 or nothing

    const int is64 = probe_is64(glabel, t);

    float np = 0.f, ll = 0.f, cm = 0.f, ca = 0.f;

    if (act) {
        int lab[4];
        load_labels(glabel, b, n0, is64, lab);

        // ---- online log-softmax over C=81 (1 exp / element) ----
        const float* pl = plabel + (size_t)b * C_ * N_ + n0;
        float m[4], s[4], xl[4];
        {
            float4 v = *(const float4*)pl;
            float xs[4] = {v.x, v.y, v.z, v.w};
            #pragma unroll
            for (int j = 0; j < 4; j++) {
                m[j] = xs[j];
                s[j] = 1.f;
                xl[j] = (lab[j] == 0) ? xs[j] : 0.f;
            }
        }
        #pragma unroll 4
        for (int c = 1; c < C_; c++) {
            float4 v = *(const float4*)(pl + (size_t)c * N_);
            float xs[4] = {v.x, v.y, v.z, v.w};
            #pragma unroll
            for (int j = 0; j < 4; j++) {
                float x = xs[j];
                float d = x - m[j];
                float e = __expf(d > 0.f ? -d : d);   // exp(-|d|), one MUFU
                if (d > 0.f) { s[j] = fmaf(s[j], e, 1.f); m[j] = x; }
                else         { s[j] += e; }
                if (c == lab[j]) xl[j] = x;
            }
        }
        float closs[4];
        #pragma unroll
        for (int j = 0; j < 4; j++) closs[j] = m[j] + __logf(s[j]) - xl[j];

        // ---- localization smooth-L1 ----
        float pp[4][4], gg[4][4], dd[4][4];
        #pragma unroll
        for (int k = 0; k < 4; k++) {
            float4 pv = *(const float4*)(ploc + ((size_t)b * 4 + k) * N_ + n0);
            float4 gv = *(const float4*)(gloc + ((size_t)b * 4 + k) * N_ + n0);
            float4 dv = *(const float4*)(dbox + (size_t)k * N_ + n0);
            pp[k][0]=pv.x; pp[k][1]=pv.y; pp[k][2]=pv.z; pp[k][3]=pv.w;
            gg[k][0]=gv.x; gg[k][1]=gv.y; gg[k][2]=gv.z; gg[k][3]=gv.w;
            dd[k][0]=dv.x; dd[k][1]=dv.y; dd[k][2]=dv.z; dd[k][3]=dv.w;
        }
        #pragma unroll
        for (int j = 0; j < 4; j++) {
            float gx = __fdividef(gg[0][j] - dd[0][j], dd[2][j]);
            float gy = __fdividef(gg[1][j] - dd[1][j], dd[3][j]);
            float gw = __logf(__fdividef(gg[2][j], dd[2][j]));
            float gh = __logf(__fdividef(gg[3][j], dd[3][j]));
            float loc = smooth_l1(pp[0][j] - gx) + smooth_l1(pp[1][j] - gy)
                      + smooth_l1(pp[2][j] - gw) + smooth_l1(pp[3][j] - gh);
            bool mk = lab[j] > 0;
            np += mk ? 1.f : 0.f;
            ll += mk ? loc : 0.f;
            cm += mk ? closs[j] : 0.f;
            ca += closs[j];
        }
        *(float4*)(g_closs + (size_t)b * N_ + n0) =
            make_float4(closs[0], closs[1], closs[2], closs[3]);
    }

    // ---- deterministic block reduction of (np, ll, cm, ca) ----
    __shared__ float4 red[THREADS];
    red[t] = make_float4(np, ll, cm, ca);
    __syncthreads();
    for (int st = THREADS / 2; st > 0; st >>= 1) {
        if (t < st) {
            float4 a = red[t], c4 = red[t + st];
            red[t] = make_float4(a.x + c4.x, a.y + c4.y, a.z + c4.z, a.w + c4.w);
        }
        __syncthreads();
    }
    if (t == 0) {
        float* o = &g_part[(b * TILES + tile) * 4];
        float4 r = red[0];
        o[0] = r.x; o[1] = r.y; o[2] = r.z; o[3] = r.w;
    }
}

// Single-block finalize: reduce partials, per-batch scale, mean.
// Exact hard-negative-mining fallback (counting rank) if 3*num_pos < N;
// with this data distribution neg_mask is all-true so the fast path runs.
__global__ __launch_bounds__(256) void mbl_k2(
    const void* __restrict__ glabel, float* __restrict__ out)
{
    __shared__ float s_np[B_], s_loc[B_], s_cm[B_], s_sel[B_];
    __shared__ int   s_fb[B_];
    __shared__ float s_con[N_];          // 34.9 KB
    __shared__ float red[256];
    const int t = threadIdx.x;
    const int is64 = probe_is64(glabel, t);

    if (t < B_) {
        float np = 0.f, ll = 0.f, cm = 0.f, ca = 0.f;
        #pragma unroll
        for (int i = 0; i < TILES; i++) {
            float4 p = *(const float4*)&g_part[(t * TILES + i) * 4];
            np += p.x; ll += p.y; cm += p.z; ca += p.w;
        }
        s_np[t] = np; s_loc[t] = ll; s_cm[t] = cm;
        s_sel[t] = ca;                       // default: neg_mask all-true
        int npi = (int)np;
        s_fb[t] = (npi > 0 && 3 * npi < N_) ? 1 : 0;
    }
    __syncthreads();

    for (int b = 0; b < B_; b++) {
        if (!s_fb[b]) continue;              // uniform (shared) condition
        // build con_neg in shared
        for (int n = t; n < N_; n += 256) {
            float cl = g_closs[(size_t)b * N_ + n];
            long long lv = is64 ? ((const long long*)glabel)[(size_t)b * N_ + n]
                                : (long long)((const int*)glabel)[(size_t)b * N_ + n];
            s_con[n] = (lv > 0) ? 0.f : cl;
        }
        __syncthreads();
        int K = min(3 * (int)s_np[b], N_);
        float sel = 0.f;
        for (int n = t; n < N_; n += 256) {
            float v = s_con[n];
            int rank = 0;
            for (int q = 0; q < N_; q++) {
                float u = s_con[q];
                rank += (u > v) || (u == v && q < n);
            }
            if (rank < K) sel += g_closs[(size_t)b * N_ + n];
        }
        red[t] = sel; __syncthreads();
        for (int st = 128; st > 0; st >>= 1) {
            if (t < st) red[t] += red[t + st];
            __syncthreads();
        }
        if (t == 0) s_sel[b] = red[0];
        __syncthreads();
    }

    __shared__ float vals[B_];
    if (t < B_) {
        float np = s_np[t];
        float total = s_loc[t] + s_cm[t] + s_sel[t];
        float nm = np > 0.f ? 1.f : 0.f;
        float npos = fmaxf(np, 1e-6f);
        vals[t] = total * nm / npos;
    }
    __syncthreads();
    if (t == 0) {
        float sum = 0.f;
        for (int i = 0; i < B_; i++) sum += vals[i];
        out[0] = sum / (float)B_;
    }
}

extern "C" void kernel_launch(void* const* d_in, const int* in_sizes, int n_in,
                              void* d_out, int out_size)
{
    const float* ploc   = (const float*)d_in[0];
    const float* plabel = (const float*)d_in[1];
    const float* gloc   = (const float*)d_in[2];
    const void*  glabel = d_in[3];
    const float* dbox   = (const float*)d_in[4];

    mbl_k1<<<dim3(TILES, B_), THREADS>>>(ploc, plabel, gloc, glabel, dbox);
    mbl_k2<<<1, 256>>>(glabel, (float*)d_out);
}